// round 9
// baseline (speedup 1.0000x reference)
#include <cuda_runtime.h>
#include <math.h>
#include <stdint.h>

#define FULL 0xffffffffu

// Problem constants
#define Bz 2
#define Sdim 2048
#define Edim 256
#define Hn 8
#define HD 32
#define WIN 129
#define OFF 64
#define MTOK (Bz*Sdim)          // 4096 token rows

// Scratch (no cudaMalloc allowed)
__device__ float g_xpe[MTOK*Edim];
__device__ float g_q[MTOK*Edim];
__device__ float g_k[MTOK*Edim];
__device__ float g_v[MTOK*Edim];
__device__ float g_ctx[MTOK*Edim];

__device__ __forceinline__ void split_tf32(float x, uint32_t& hi, uint32_t& lo) {
    asm("cvt.rna.tf32.f32 %0, %1;" : "=r"(hi) : "f"(x));
    float l = x - __uint_as_float(hi);
    asm("cvt.rna.tf32.f32 %0, %1;" : "=r"(lo) : "f"(l));
}
__device__ __forceinline__ void split4(float4 x, float4& h, float4& l) {
    uint32_t hi, lo;
    split_tf32(x.x, hi, lo); h.x = __uint_as_float(hi); l.x = __uint_as_float(lo);
    split_tf32(x.y, hi, lo); h.y = __uint_as_float(hi); l.y = __uint_as_float(lo);
    split_tf32(x.z, hi, lo); h.z = __uint_as_float(hi); l.z = __uint_as_float(lo);
    split_tf32(x.w, hi, lo); h.w = __uint_as_float(hi); l.w = __uint_as_float(lo);
}
__device__ __forceinline__ void mma_tf32(float* acc, const uint32_t* a, const uint32_t* b) {
    asm volatile(
        "mma.sync.aligned.m16n8k8.row.col.f32.tf32.tf32.f32 "
        "{%0,%1,%2,%3}, {%4,%5,%6,%7}, {%8,%9}, {%0,%1,%2,%3};\n"
        : "+f"(acc[0]), "+f"(acc[1]), "+f"(acc[2]), "+f"(acc[3])
        : "r"(a[0]), "r"(a[1]), "r"(a[2]), "r"(a[3]), "r"(b[0]), "r"(b[1]));
}

// ---------------------------------------------------------------------------
// x + sinusoidal positional encoding
// ---------------------------------------------------------------------------
__global__ void add_pe_kernel(const float* __restrict__ x, float* __restrict__ y) {
    int i = blockIdx.x * 256 + threadIdx.x;
    int e = i & (Edim - 1);
    int s = (i >> 8) & (Sdim - 1);
    float dv = expf((float)(e >> 1) * (-2.0f * 9.210340371976184f / 256.0f));
    float ang = (float)s * dv;
    float pe = (e & 1) ? cosf(ang) : sinf(ang);
    y[i] = x[i] + pe;
}

// ---------------------------------------------------------------------------
// 3xTF32 tensor-core GEMM: Y[M,256] = X[M,256] @ W[256,256] + bias
// Producer: LDG.128 -> tf32 hi/lo split in regs -> STS (off critical path).
// Consumer: pure LDS + MMA (no ALU in chain).
// CTA tile 64x64, 128 threads (4 warps, warp tile 32x32, 2x4 m16n8k8 frags).
// K chunk 16, double-buffered smem, register-pipelined loads.
// ---------------------------------------------------------------------------
#define GBM 64
#define GBN 64
#define GBK 16
#define APAD 20
#define BPAD 72

__global__ __launch_bounds__(128) void gemm_tc_kernel(
    const float* __restrict__ X,
    const float* __restrict__ W0, const float* __restrict__ b0, float* __restrict__ Y0,
    const float* __restrict__ W1, const float* __restrict__ b1, float* __restrict__ Y1,
    const float* __restrict__ W2, const float* __restrict__ b2, float* __restrict__ Y2)
{
    __shared__ float Ah[2][GBM][APAD];
    __shared__ float Al[2][GBM][APAD];
    __shared__ float Bh[2][GBK][BPAD];
    __shared__ float Bl[2][GBK][BPAD];

    const int t    = threadIdx.x;
    const int lane = t & 31;
    const int warp = t >> 5;
    const int warp_m = warp & 1;
    const int warp_n = warp >> 1;

    const int bm = blockIdx.x * GBM;
    const int wsel = blockIdx.y >> 2;
    const int bn = (blockIdx.y & 3) * GBN;

    const float* W    = (wsel == 0) ? W0 : ((wsel == 1) ? W1 : W2);
    const float* bias = (wsel == 0) ? b0 : ((wsel == 1) ? b1 : b2);
    float*       Y    = (wsel == 0) ? Y0 : ((wsel == 1) ? Y1 : Y2);

    float acc[2][4][4];
#pragma unroll
    for (int mf = 0; mf < 2; ++mf)
#pragma unroll
        for (int nf = 0; nf < 4; ++nf)
#pragma unroll
            for (int r = 0; r < 4; ++r) acc[mf][nf][r] = 0.f;

    // Loader indices: A 64x16 = 2 float4/thr (rows am, am+32); B 16x64 = 2 float4/thr
    const int am  = t >> 2;
    const int akq = (t & 3) * 4;
    const int bkk = t >> 4;
    const int bnq = (t & 15) * 4;

    float4 ra0, ra1, rb0, rb1;   // register prefetch

#define LDG_T(it)                                                          \
    do {                                                                   \
        int k0_ = (it) * GBK;                                              \
        ra0 = *(const float4*)&X[(bm + am) * Edim + k0_ + akq];            \
        ra1 = *(const float4*)&X[(bm + am + 32) * Edim + k0_ + akq];       \
        rb0 = *(const float4*)&W[(k0_ + bkk) * Edim + bn + bnq];           \
        rb1 = *(const float4*)&W[(k0_ + bkk + 8) * Edim + bn + bnq];       \
    } while (0)

#define STS_T(buf)                                                         \
    do {                                                                   \
        float4 h_, l_;                                                     \
        split4(ra0, h_, l_);                                               \
        *(float4*)&Ah[buf][am][akq] = h_;                                  \
        *(float4*)&Al[buf][am][akq] = l_;                                  \
        split4(ra1, h_, l_);                                               \
        *(float4*)&Ah[buf][am + 32][akq] = h_;                             \
        *(float4*)&Al[buf][am + 32][akq] = l_;                             \
        split4(rb0, h_, l_);                                               \
        *(float4*)&Bh[buf][bkk][bnq] = h_;                                 \
        *(float4*)&Bl[buf][bkk][bnq] = l_;                                 \
        split4(rb1, h_, l_);                                               \
        *(float4*)&Bh[buf][bkk + 8][bnq] = h_;                             \
        *(float4*)&Bl[buf][bkk + 8][bnq] = l_;                             \
    } while (0)

    LDG_T(0);
    STS_T(0);
    __syncthreads();

    const int KITERS = Edim / GBK;   // 16
    for (int it = 0; it < KITERS; ++it) {
        int buf = it & 1;
        bool more = (it + 1 < KITERS);
        if (more) LDG_T(it + 1);

        // ---- consumer: pure LDS + MMA ----
#pragma unroll
        for (int ks = 0; ks < 2; ++ks) {
            const int kk = ks * 8 + (lane & 3);
            uint32_t ah[2][4], al[2][4], bh[4][2], bl[4][2];
#pragma unroll
            for (int mf = 0; mf < 2; ++mf) {
                int r = warp_m * 32 + mf * 16 + (lane >> 2);
                ah[mf][0] = __float_as_uint(Ah[buf][r][kk]);
                ah[mf][1] = __float_as_uint(Ah[buf][r + 8][kk]);
                ah[mf][2] = __float_as_uint(Ah[buf][r][kk + 4]);
                ah[mf][3] = __float_as_uint(Ah[buf][r + 8][kk + 4]);
                al[mf][0] = __float_as_uint(Al[buf][r][kk]);
                al[mf][1] = __float_as_uint(Al[buf][r + 8][kk]);
                al[mf][2] = __float_as_uint(Al[buf][r][kk + 4]);
                al[mf][3] = __float_as_uint(Al[buf][r + 8][kk + 4]);
            }
#pragma unroll
            for (int nf = 0; nf < 4; ++nf) {
                int cn = warp_n * 32 + nf * 8 + (lane >> 2);
                bh[nf][0] = __float_as_uint(Bh[buf][kk][cn]);
                bh[nf][1] = __float_as_uint(Bh[buf][kk + 4][cn]);
                bl[nf][0] = __float_as_uint(Bl[buf][kk][cn]);
                bl[nf][1] = __float_as_uint(Bl[buf][kk + 4][cn]);
            }
#pragma unroll
            for (int mf = 0; mf < 2; ++mf)
#pragma unroll
                for (int nf = 0; nf < 4; ++nf) {
                    mma_tf32(acc[mf][nf], al[mf], bh[nf]);   // lo*hi
                    mma_tf32(acc[mf][nf], ah[mf], bl[nf]);   // hi*lo
                    mma_tf32(acc[mf][nf], ah[mf], bh[nf]);   // hi*hi
                }
        }

        if (more) STS_T(buf ^ 1);
        __syncthreads();
    }

    // ---- epilogue: bias + store ----
#pragma unroll
    for (int mf = 0; mf < 2; ++mf) {
        int r = bm + warp_m * 32 + mf * 16 + (lane >> 2);
#pragma unroll
        for (int nf = 0; nf < 4; ++nf) {
            int cg = bn + warp_n * 32 + nf * 8 + 2 * (lane & 3);
            float bv0 = bias[cg], bv1 = bias[cg + 1];
            float2 v0 = make_float2(acc[mf][nf][0] + bv0, acc[mf][nf][1] + bv1);
            float2 v1 = make_float2(acc[mf][nf][2] + bv0, acc[mf][nf][3] + bv1);
            *(float2*)&Y[r * Edim + cg] = v0;
            *(float2*)&Y[(r + 8) * Edim + cg] = v1;
        }
    }
#undef LDG_T
#undef STS_T
}

// ---------------------------------------------------------------------------
// Tensor-core windowed attention (unchanged from R8).
// Block: 256 thr (8 warps), 32 queries for one (b,h). Key rows 160.
// ---------------------------------------------------------------------------
#define KP 36     // k_sm / q_sm row pad
#define VP 40     // v_sm row pad
#define PP 164    // p_sm row pad
#define NROWS 160

#define SM_K 0
#define SM_V (SM_K + NROWS*KP)            // 5760
#define SM_Q (SM_V + NROWS*VP)            // 12160
#define SM_P (SM_Q + 32*KP)               // 13312
#define SM_RMAX (SM_P + 32*PP)            // 18560
#define SM_RSUM (SM_RMAX + 128)           // 18688
#define SM_TOT (SM_RSUM + 128)            // 18816 floats = 75264 B

__global__ __launch_bounds__(256) void attn_kernel(
    const float* __restrict__ q, const float* __restrict__ k,
    const float* __restrict__ v, float* __restrict__ ctx,
    float* __restrict__ attn_out)
{
    extern __shared__ float sm[];
    float* k_sm = sm + SM_K;
    float* v_sm = sm + SM_V;
    float* q_sm = sm + SM_Q;
    float* p_sm = sm + SM_P;
    float* rmax = sm + SM_RMAX;
    float* rsum = sm + SM_RSUM;

    const int b    = blockIdx.z;
    const int h    = blockIdx.y;
    const int s0   = blockIdx.x * 32;
    const int t    = threadIdx.x;
    const int lane = t & 31;
    const int warp = t >> 5;
    const int warp_m = warp & 1;
    const int warp_n = warp >> 1;
    const int lr = lane >> 2;
    const int lc = lane & 3;

    const int base = (b * Sdim) * Edim + h * HD;

#pragma unroll
    for (int it = 0; it < NROWS / 8; ++it) {
        int r = warp + it * 8;
        int tok = min(max(s0 - OFF + r, 0), Sdim - 1);
        int g = base + tok * Edim + lane;
        k_sm[r * KP + lane] = k[g];
        v_sm[r * VP + lane] = v[g];
    }
    {
        int qq = warp * 4;
#pragma unroll
        for (int i = 0; i < 4; ++i)
            q_sm[(qq + i) * KP + lane] = q[base + (s0 + qq + i) * Edim + lane];
    }
    __syncthreads();

    float acc[5][4];
#pragma unroll
    for (int nt = 0; nt < 5; ++nt)
#pragma unroll
        for (int j = 0; j < 4; ++j) acc[nt][j] = 0.f;

#pragma unroll
    for (int kt = 0; kt < 4; ++kt) {
        int kb = kt * 8 + lc;
        uint32_t ah[4], al[4];
        split_tf32(q_sm[(warp_m*16 + lr    ) * KP + kb    ], ah[0], al[0]);
        split_tf32(q_sm[(warp_m*16 + lr + 8) * KP + kb    ], ah[1], al[1]);
        split_tf32(q_sm[(warp_m*16 + lr    ) * KP + kb + 4], ah[2], al[2]);
        split_tf32(q_sm[(warp_m*16 + lr + 8) * KP + kb + 4], ah[3], al[3]);
#pragma unroll
        for (int nt = 0; nt < 5; ++nt) {
            int key = warp_n * 40 + nt * 8 + lr;
            uint32_t bh[2], bl[2];
            split_tf32(k_sm[key * KP + kb    ], bh[0], bl[0]);
            split_tf32(k_sm[key * KP + kb + 4], bh[1], bl[1]);
            mma_tf32(acc[nt], al, bh);
            mma_tf32(acc[nt], ah, bl);
            mma_tf32(acc[nt], ah, bh);
        }
    }

    const float scale = 0.17677669529663689f;  // 1/sqrt(32)
    const int q0 = warp_m * 16 + lr;
    const int q1 = q0 + 8;
    float m0 = -INFINITY, m1 = -INFINITY;
#pragma unroll
    for (int nt = 0; nt < 5; ++nt) {
#pragma unroll
        for (int j = 0; j < 4; ++j) {
            int row = (j >= 2) ? q1 : q0;
            int key = warp_n * 40 + nt * 8 + 2 * lc + (j & 1);
            int w  = key - row;
            int kg = s0 - OFF + key;
            bool valid = (w >= 0) & (w <= 128) & (kg >= 0) & (kg < Sdim);
            float s = valid ? acc[nt][j] * scale : -1e9f;
            acc[nt][j] = s;
            if (j >= 2) m1 = fmaxf(m1, s); else m0 = fmaxf(m0, s);
        }
    }
    m0 = fmaxf(m0, __shfl_xor_sync(FULL, m0, 1));
    m0 = fmaxf(m0, __shfl_xor_sync(FULL, m0, 2));
    m1 = fmaxf(m1, __shfl_xor_sync(FULL, m1, 1));
    m1 = fmaxf(m1, __shfl_xor_sync(FULL, m1, 2));
    if (lc == 0) { rmax[q0 * 4 + warp_n] = m0; rmax[q1 * 4 + warp_n] = m1; }
    __syncthreads();

    float4 t0 = *(const float4*)&rmax[q0 * 4];
    float4 t1 = *(const float4*)&rmax[q1 * 4];
    float gm0 = fmaxf(fmaxf(t0.x, t0.y), fmaxf(t0.z, t0.w));
    float gm1 = fmaxf(fmaxf(t1.x, t1.y), fmaxf(t1.z, t1.w));

    float sum0 = 0.f, sum1 = 0.f;
#pragma unroll
    for (int nt = 0; nt < 5; ++nt) {
#pragma unroll
        for (int j = 0; j < 4; ++j) {
            float e = expf(acc[nt][j] - ((j >= 2) ? gm1 : gm0));
            acc[nt][j] = e;
            if (j >= 2) sum1 += e; else sum0 += e;
        }
    }
    sum0 += __shfl_xor_sync(FULL, sum0, 1);
    sum0 += __shfl_xor_sync(FULL, sum0, 2);
    sum1 += __shfl_xor_sync(FULL, sum1, 1);
    sum1 += __shfl_xor_sync(FULL, sum1, 2);
    if (lc == 0) { rsum[q0 * 4 + warp_n] = sum0; rsum[q1 * 4 + warp_n] = sum1; }
    __syncthreads();

    float4 u0 = *(const float4*)&rsum[q0 * 4];
    float4 u1 = *(const float4*)&rsum[q1 * 4];
    float inv0 = 1.f / (u0.x + u0.y + u0.z + u0.w);
    float inv1 = 1.f / (u1.x + u1.y + u1.z + u1.w);

#pragma unroll
    for (int nt = 0; nt < 5; ++nt) {
#pragma unroll
        for (int j = 0; j < 4; ++j) {
            int row = (j >= 2) ? q1 : q0;
            int key = warp_n * 40 + nt * 8 + 2 * lc + (j & 1);
            p_sm[row * PP + key] = acc[nt][j] * ((j >= 2) ? inv1 : inv0);
        }
    }
    __syncthreads();

    if (attn_out) {
        int qrow = warp * 4;
#pragma unroll
        for (int i = 0; i < 4; ++i) {
            int qq = qrow + i;
            int arow = ((b * Hn + h) * Sdim + s0 + qq) * WIN;
#pragma unroll
            for (int j = 0; j < 4; ++j)
                attn_out[arow + lane + 32 * j] = p_sm[qq * PP + qq + lane + 32 * j];
            if (lane == 0)
                attn_out[arow + 128] = p_sm[qq * PP + qq + 128];
        }
    }

    float c[4] = {0.f, 0.f, 0.f, 0.f};
#pragma unroll
    for (int kt = 0; kt < 20; ++kt) {
        int kb = kt * 8 + lc;
        uint32_t ah[4], al[4], bh[2], bl[2];
        split_tf32(p_sm[q0 * PP + kb    ], ah[0], al[0]);
        split_tf32(p_sm[q1 * PP + kb    ], ah[1], al[1]);
        split_tf32(p_sm[q0 * PP + kb + 4], ah[2], al[2]);
        split_tf32(p_sm[q1 * PP + kb + 4], ah[3], al[3]);
        split_tf32(v_sm[(kb    ) * VP + warp_n * 8 + lr], bh[0], bl[0]);
        split_tf32(v_sm[(kb + 4) * VP + warp_n * 8 + lr], bh[1], bl[1]);
        mma_tf32(c, al, bh);
        mma_tf32(c, ah, bl);
        mma_tf32(c, ah, bh);
    }

    int dcol = warp_n * 8 + 2 * lc;
    *(float2*)&ctx[base + (s0 + q0) * Edim + dcol] = make_float2(c[0], c[1]);
    *(float2*)&ctx[base + (s0 + q1) * Edim + dcol] = make_float2(c[2], c[3]);
}

// ---------------------------------------------------------------------------
extern "C" void kernel_launch(void* const* d_in, const int* in_sizes, int n_in,
                              void* d_out, int out_size) {
    const float* x  = (const float*)d_in[0];
    const float* Wq = (const float*)d_in[1];
    const float* bq = (const float*)d_in[2];
    const float* Wk = (const float*)d_in[3];
    const float* bk = (const float*)d_in[4];
    const float* Wv = (const float*)d_in[5];
    const float* bv = (const float*)d_in[6];
    const float* Wo = (const float*)d_in[7];
    const float* bo = (const float*)d_in[8];
    float* out = (float*)d_out;

    float *xpe, *q, *k, *v, *ctx;
    cudaGetSymbolAddress((void**)&xpe, g_xpe);
    cudaGetSymbolAddress((void**)&q,   g_q);
    cudaGetSymbolAddress((void**)&k,   g_k);
    cudaGetSymbolAddress((void**)&v,   g_v);
    cudaGetSymbolAddress((void**)&ctx, g_ctx);

    const long OUT_ELEMS  = (long)Bz * Sdim * Edim;                 // 1,048,576
    const long ATTN_ELEMS = (long)Bz * Hn * Sdim * WIN;             // 4,227,072
    float* attn_out = nullptr;
    if ((long)out_size >= OUT_ELEMS + ATTN_ELEMS) attn_out = out + OUT_ELEMS;

    static bool attr_set = false;
    if (!attr_set) {
        cudaFuncSetAttribute(attn_kernel,
                             cudaFuncAttributeMaxDynamicSharedMemorySize,
                             SM_TOT * 4);
        attr_set = true;
    }

    add_pe_kernel<<<MTOK * Edim / 256, 256>>>(x, xpe);

    // Fused Q/K/V projections: grid.y 0-3 -> Wq, 4-7 -> Wk, 8-11 -> Wv
    gemm_tc_kernel<<<dim3(MTOK / GBM, 12), 128>>>(
        xpe, Wq, bq, q, Wk, bk, k, Wv, bv, v);

    attn_kernel<<<dim3(Sdim / 32, Hn, Bz), 256, SM_TOT * 4>>>(
        q, k, v, ctx, attn_out);

    // Output projection: grid.y 0-3 -> Wo only
    gemm_tc_kernel<<<dim3(MTOK / GBM, 4), 128>>>(
        ctx, Wo, bo, out, Wo, bo, out, Wo, bo, out);
}

// round 10
// speedup vs baseline: 1.0417x; 1.0417x over previous
#include <cuda_runtime.h>
#include <math.h>
#include <stdint.h>

#define FULL 0xffffffffu

// Problem constants
#define Bz 2
#define Sdim 2048
#define Edim 256
#define Hn 8
#define HD 32
#define WIN 129
#define OFF 64
#define MTOK (Bz*Sdim)          // 4096 token rows

// Scratch (no cudaMalloc allowed)
__device__ float g_xpe[MTOK*Edim];
__device__ float g_q[MTOK*Edim];
__device__ float g_k[MTOK*Edim];
__device__ float g_v[MTOK*Edim];
__device__ float g_ctx[MTOK*Edim];

__device__ __forceinline__ void split_tf32(float x, uint32_t& hi, uint32_t& lo) {
    asm("cvt.rna.tf32.f32 %0, %1;" : "=r"(hi) : "f"(x));
    float l = x - __uint_as_float(hi);
    asm("cvt.rna.tf32.f32 %0, %1;" : "=r"(lo) : "f"(l));
}
__device__ __forceinline__ void mma_tf32(float* acc, const uint32_t* a, const uint32_t* b) {
    asm volatile(
        "mma.sync.aligned.m16n8k8.row.col.f32.tf32.tf32.f32 "
        "{%0,%1,%2,%3}, {%4,%5,%6,%7}, {%8,%9}, {%0,%1,%2,%3};\n"
        : "+f"(acc[0]), "+f"(acc[1]), "+f"(acc[2]), "+f"(acc[3])
        : "r"(a[0]), "r"(a[1]), "r"(a[2]), "r"(a[3]), "r"(b[0]), "r"(b[1]));
}
__device__ __forceinline__ void cp16(void* smem, const void* g) {
    uint32_t s = (uint32_t)__cvta_generic_to_shared(smem);
    asm volatile("cp.async.cg.shared.global [%0], [%1], 16;\n" :: "r"(s), "l"(g));
}

// ---------------------------------------------------------------------------
// x + sinusoidal positional encoding
// ---------------------------------------------------------------------------
__global__ void add_pe_kernel(const float* __restrict__ x, float* __restrict__ y) {
    int i = blockIdx.x * 256 + threadIdx.x;
    int e = i & (Edim - 1);
    int s = (i >> 8) & (Sdim - 1);
    float dv = expf((float)(e >> 1) * (-2.0f * 9.210340371976184f / 256.0f));
    float ang = (float)s * dv;
    float pe = (e & 1) ? cosf(ang) : sinf(ang);
    y[i] = x[i] + pe;
}

// ---------------------------------------------------------------------------
// 3xTF32 tensor-core GEMM: Y[M,256] = X[M,256] @ W[256,256] + bias
// CTA tile 64x64, 128 threads (4 warps, warp tile 32x32, 2x4 m16n8k8 frags).
// K chunk 16, FOUR-stage cp.async pipeline (3 tiles in flight) so a single
// resident CTA can hide L2/DRAM latency. Split in consumer (R5 math).
// ---------------------------------------------------------------------------
#define GBM 64
#define GBN 64
#define GBK 16
#define NSTAGE 4
#define APAD 20
#define BPAD 72

__global__ __launch_bounds__(128) void gemm_tc_kernel(
    const float* __restrict__ X,
    const float* __restrict__ W0, const float* __restrict__ b0, float* __restrict__ Y0,
    const float* __restrict__ W1, const float* __restrict__ b1, float* __restrict__ Y1,
    const float* __restrict__ W2, const float* __restrict__ b2, float* __restrict__ Y2)
{
    __shared__ float As[NSTAGE][GBM][APAD];
    __shared__ float Bs[NSTAGE][GBK][BPAD];

    const int t    = threadIdx.x;
    const int lane = t & 31;
    const int warp = t >> 5;
    const int warp_m = warp & 1;
    const int warp_n = warp >> 1;

    const int bm = blockIdx.x * GBM;
    const int wsel = blockIdx.y >> 2;
    const int bn = (blockIdx.y & 3) * GBN;

    const float* W    = (wsel == 0) ? W0 : ((wsel == 1) ? W1 : W2);
    const float* bias = (wsel == 0) ? b0 : ((wsel == 1) ? b1 : b2);
    float*       Y    = (wsel == 0) ? Y0 : ((wsel == 1) ? Y1 : Y2);

    float acc[2][4][4];
#pragma unroll
    for (int mf = 0; mf < 2; ++mf)
#pragma unroll
        for (int nf = 0; nf < 4; ++nf)
#pragma unroll
            for (int r = 0; r < 4; ++r) acc[mf][nf][r] = 0.f;

    // Loader: A 64x16 (2 float4/thr, rows am & am+32), B 16x64 (2 float4/thr)
    const int am  = t >> 2;
    const int akq = (t & 3) * 4;
    const int bkk = t >> 4;
    const int bnq = (t & 15) * 4;

#define LOAD_TILE(it, buf)                                                     \
    do {                                                                       \
        int k0_ = (it) * GBK;                                                  \
        cp16(&As[buf][am][akq],      &X[(bm + am) * Edim + k0_ + akq]);        \
        cp16(&As[buf][am + 32][akq], &X[(bm + am + 32) * Edim + k0_ + akq]);   \
        cp16(&Bs[buf][bkk][bnq],     &W[(k0_ + bkk) * Edim + bn + bnq]);       \
        cp16(&Bs[buf][bkk + 8][bnq], &W[(k0_ + bkk + 8) * Edim + bn + bnq]);   \
        asm volatile("cp.async.commit_group;\n");                              \
    } while (0)

    const int KITERS = Edim / GBK;   // 16
    LOAD_TILE(0, 0);
    LOAD_TILE(1, 1);
    LOAD_TILE(2, 2);

    for (int it = 0; it < KITERS; ++it) {
        const int buf = it & (NSTAGE - 1);
        const int rem = KITERS - 1 - it;
        // wait until tile `it` has landed (own thread's groups), then barrier
        if (rem >= 2)      asm volatile("cp.async.wait_group 2;\n");
        else if (rem == 1) asm volatile("cp.async.wait_group 1;\n");
        else               asm volatile("cp.async.wait_group 0;\n");
        __syncthreads();

        // issue tile it+3 into the slot freed by tile it-1 (safe after barrier)
        if (it + 3 < KITERS) LOAD_TILE(it + 3, (it + 3) & (NSTAGE - 1));

#pragma unroll
        for (int ks = 0; ks < 2; ++ks) {
            const int kk = ks * 8 + (lane & 3);
            uint32_t ah[2][4], al[2][4], bh[4][2], bl[4][2];
#pragma unroll
            for (int mf = 0; mf < 2; ++mf) {
                int r = warp_m * 32 + mf * 16 + (lane >> 2);
                split_tf32(As[buf][r][kk],          ah[mf][0], al[mf][0]);
                split_tf32(As[buf][r + 8][kk],      ah[mf][1], al[mf][1]);
                split_tf32(As[buf][r][kk + 4],      ah[mf][2], al[mf][2]);
                split_tf32(As[buf][r + 8][kk + 4],  ah[mf][3], al[mf][3]);
            }
#pragma unroll
            for (int nf = 0; nf < 4; ++nf) {
                int cn = warp_n * 32 + nf * 8 + (lane >> 2);
                split_tf32(Bs[buf][kk][cn],     bh[nf][0], bl[nf][0]);
                split_tf32(Bs[buf][kk + 4][cn], bh[nf][1], bl[nf][1]);
            }
#pragma unroll
            for (int mf = 0; mf < 2; ++mf)
#pragma unroll
                for (int nf = 0; nf < 4; ++nf) {
                    mma_tf32(acc[mf][nf], al[mf], bh[nf]);   // lo*hi
                    mma_tf32(acc[mf][nf], ah[mf], bl[nf]);   // hi*lo
                    mma_tf32(acc[mf][nf], ah[mf], bh[nf]);   // hi*hi
                }
        }
        __syncthreads();
    }

    // ---- epilogue: bias + store ----
#pragma unroll
    for (int mf = 0; mf < 2; ++mf) {
        int r = bm + warp_m * 32 + mf * 16 + (lane >> 2);
#pragma unroll
        for (int nf = 0; nf < 4; ++nf) {
            int cg = bn + warp_n * 32 + nf * 8 + 2 * (lane & 3);
            float bv0 = bias[cg], bv1 = bias[cg + 1];
            float2 v0 = make_float2(acc[mf][nf][0] + bv0, acc[mf][nf][1] + bv1);
            float2 v1 = make_float2(acc[mf][nf][2] + bv0, acc[mf][nf][3] + bv1);
            *(float2*)&Y[r * Edim + cg] = v0;
            *(float2*)&Y[(r + 8) * Edim + cg] = v1;
        }
    }
#undef LOAD_TILE
}

// ---------------------------------------------------------------------------
// Tensor-core windowed attention (unchanged from R8).
// Block: 256 thr (8 warps), 32 queries for one (b,h). Key rows 160.
// ---------------------------------------------------------------------------
#define KP 36     // k_sm / q_sm row pad
#define VP 40     // v_sm row pad
#define PP 164    // p_sm row pad
#define NROWS 160

#define SM_K 0
#define SM_V (SM_K + NROWS*KP)            // 5760
#define SM_Q (SM_V + NROWS*VP)            // 12160
#define SM_P (SM_Q + 32*KP)               // 13312
#define SM_RMAX (SM_P + 32*PP)            // 18560
#define SM_RSUM (SM_RMAX + 128)           // 18688
#define SM_TOT (SM_RSUM + 128)            // 18816 floats = 75264 B

__global__ __launch_bounds__(256) void attn_kernel(
    const float* __restrict__ q, const float* __restrict__ k,
    const float* __restrict__ v, float* __restrict__ ctx,
    float* __restrict__ attn_out)
{
    extern __shared__ float sm[];
    float* k_sm = sm + SM_K;
    float* v_sm = sm + SM_V;
    float* q_sm = sm + SM_Q;
    float* p_sm = sm + SM_P;
    float* rmax = sm + SM_RMAX;
    float* rsum = sm + SM_RSUM;

    const int b    = blockIdx.z;
    const int h    = blockIdx.y;
    const int s0   = blockIdx.x * 32;
    const int t    = threadIdx.x;
    const int lane = t & 31;
    const int warp = t >> 5;
    const int warp_m = warp & 1;
    const int warp_n = warp >> 1;
    const int lr = lane >> 2;
    const int lc = lane & 3;

    const int base = (b * Sdim) * Edim + h * HD;

#pragma unroll
    for (int it = 0; it < NROWS / 8; ++it) {
        int r = warp + it * 8;
        int tok = min(max(s0 - OFF + r, 0), Sdim - 1);
        int g = base + tok * Edim + lane;
        k_sm[r * KP + lane] = k[g];
        v_sm[r * VP + lane] = v[g];
    }
    {
        int qq = warp * 4;
#pragma unroll
        for (int i = 0; i < 4; ++i)
            q_sm[(qq + i) * KP + lane] = q[base + (s0 + qq + i) * Edim + lane];
    }
    __syncthreads();

    float acc[5][4];
#pragma unroll
    for (int nt = 0; nt < 5; ++nt)
#pragma unroll
        for (int j = 0; j < 4; ++j) acc[nt][j] = 0.f;

#pragma unroll
    for (int kt = 0; kt < 4; ++kt) {
        int kb = kt * 8 + lc;
        uint32_t ah[4], al[4];
        split_tf32(q_sm[(warp_m*16 + lr    ) * KP + kb    ], ah[0], al[0]);
        split_tf32(q_sm[(warp_m*16 + lr + 8) * KP + kb    ], ah[1], al[1]);
        split_tf32(q_sm[(warp_m*16 + lr    ) * KP + kb + 4], ah[2], al[2]);
        split_tf32(q_sm[(warp_m*16 + lr + 8) * KP + kb + 4], ah[3], al[3]);
#pragma unroll
        for (int nt = 0; nt < 5; ++nt) {
            int key = warp_n * 40 + nt * 8 + lr;
            uint32_t bh[2], bl[2];
            split_tf32(k_sm[key * KP + kb    ], bh[0], bl[0]);
            split_tf32(k_sm[key * KP + kb + 4], bh[1], bl[1]);
            mma_tf32(acc[nt], al, bh);
            mma_tf32(acc[nt], ah, bl);
            mma_tf32(acc[nt], ah, bh);
        }
    }

    const float scale = 0.17677669529663689f;  // 1/sqrt(32)
    const int q0 = warp_m * 16 + lr;
    const int q1 = q0 + 8;
    float m0 = -INFINITY, m1 = -INFINITY;
#pragma unroll
    for (int nt = 0; nt < 5; ++nt) {
#pragma unroll
        for (int j = 0; j < 4; ++j) {
            int row = (j >= 2) ? q1 : q0;
            int key = warp_n * 40 + nt * 8 + 2 * lc + (j & 1);
            int w  = key - row;
            int kg = s0 - OFF + key;
            bool valid = (w >= 0) & (w <= 128) & (kg >= 0) & (kg < Sdim);
            float s = valid ? acc[nt][j] * scale : -1e9f;
            acc[nt][j] = s;
            if (j >= 2) m1 = fmaxf(m1, s); else m0 = fmaxf(m0, s);
        }
    }
    m0 = fmaxf(m0, __shfl_xor_sync(FULL, m0, 1));
    m0 = fmaxf(m0, __shfl_xor_sync(FULL, m0, 2));
    m1 = fmaxf(m1, __shfl_xor_sync(FULL, m1, 1));
    m1 = fmaxf(m1, __shfl_xor_sync(FULL, m1, 2));
    if (lc == 0) { rmax[q0 * 4 + warp_n] = m0; rmax[q1 * 4 + warp_n] = m1; }
    __syncthreads();

    float4 t0 = *(const float4*)&rmax[q0 * 4];
    float4 t1 = *(const float4*)&rmax[q1 * 4];
    float gm0 = fmaxf(fmaxf(t0.x, t0.y), fmaxf(t0.z, t0.w));
    float gm1 = fmaxf(fmaxf(t1.x, t1.y), fmaxf(t1.z, t1.w));

    float sum0 = 0.f, sum1 = 0.f;
#pragma unroll
    for (int nt = 0; nt < 5; ++nt) {
#pragma unroll
        for (int j = 0; j < 4; ++j) {
            float e = expf(acc[nt][j] - ((j >= 2) ? gm1 : gm0));
            acc[nt][j] = e;
            if (j >= 2) sum1 += e; else sum0 += e;
        }
    }
    sum0 += __shfl_xor_sync(FULL, sum0, 1);
    sum0 += __shfl_xor_sync(FULL, sum0, 2);
    sum1 += __shfl_xor_sync(FULL, sum1, 1);
    sum1 += __shfl_xor_sync(FULL, sum1, 2);
    if (lc == 0) { rsum[q0 * 4 + warp_n] = sum0; rsum[q1 * 4 + warp_n] = sum1; }
    __syncthreads();

    float4 u0 = *(const float4*)&rsum[q0 * 4];
    float4 u1 = *(const float4*)&rsum[q1 * 4];
    float inv0 = 1.f / (u0.x + u0.y + u0.z + u0.w);
    float inv1 = 1.f / (u1.x + u1.y + u1.z + u1.w);

#pragma unroll
    for (int nt = 0; nt < 5; ++nt) {
#pragma unroll
        for (int j = 0; j < 4; ++j) {
            int row = (j >= 2) ? q1 : q0;
            int key = warp_n * 40 + nt * 8 + 2 * lc + (j & 1);
            p_sm[row * PP + key] = acc[nt][j] * ((j >= 2) ? inv1 : inv0);
        }
    }
    __syncthreads();

    if (attn_out) {
        int qrow = warp * 4;
#pragma unroll
        for (int i = 0; i < 4; ++i) {
            int qq = qrow + i;
            int arow = ((b * Hn + h) * Sdim + s0 + qq) * WIN;
#pragma unroll
            for (int j = 0; j < 4; ++j)
                attn_out[arow + lane + 32 * j] = p_sm[qq * PP + qq + lane + 32 * j];
            if (lane == 0)
                attn_out[arow + 128] = p_sm[qq * PP + qq + 128];
        }
    }

    float c[4] = {0.f, 0.f, 0.f, 0.f};
#pragma unroll
    for (int kt = 0; kt < 20; ++kt) {
        int kb = kt * 8 + lc;
        uint32_t ah[4], al[4], bh[2], bl[2];
        split_tf32(p_sm[q0 * PP + kb    ], ah[0], al[0]);
        split_tf32(p_sm[q1 * PP + kb    ], ah[1], al[1]);
        split_tf32(p_sm[q0 * PP + kb + 4], ah[2], al[2]);
        split_tf32(p_sm[q1 * PP + kb + 4], ah[3], al[3]);
        split_tf32(v_sm[(kb    ) * VP + warp_n * 8 + lr], bh[0], bl[0]);
        split_tf32(v_sm[(kb + 4) * VP + warp_n * 8 + lr], bh[1], bl[1]);
        mma_tf32(c, al, bh);
        mma_tf32(c, ah, bl);
        mma_tf32(c, ah, bh);
    }

    int dcol = warp_n * 8 + 2 * lc;
    *(float2*)&ctx[base + (s0 + q0) * Edim + dcol] = make_float2(c[0], c[1]);
    *(float2*)&ctx[base + (s0 + q1) * Edim + dcol] = make_float2(c[2], c[3]);
}

// ---------------------------------------------------------------------------
extern "C" void kernel_launch(void* const* d_in, const int* in_sizes, int n_in,
                              void* d_out, int out_size) {
    const float* x  = (const float*)d_in[0];
    const float* Wq = (const float*)d_in[1];
    const float* bq = (const float*)d_in[2];
    const float* Wk = (const float*)d_in[3];
    const float* bk = (const float*)d_in[4];
    const float* Wv = (const float*)d_in[5];
    const float* bv = (const float*)d_in[6];
    const float* Wo = (const float*)d_in[7];
    const float* bo = (const float*)d_in[8];
    float* out = (float*)d_out;

    float *xpe, *q, *k, *v, *ctx;
    cudaGetSymbolAddress((void**)&xpe, g_xpe);
    cudaGetSymbolAddress((void**)&q,   g_q);
    cudaGetSymbolAddress((void**)&k,   g_k);
    cudaGetSymbolAddress((void**)&v,   g_v);
    cudaGetSymbolAddress((void**)&ctx, g_ctx);

    const long OUT_ELEMS  = (long)Bz * Sdim * Edim;                 // 1,048,576
    const long ATTN_ELEMS = (long)Bz * Hn * Sdim * WIN;             // 4,227,072
    float* attn_out = nullptr;
    if ((long)out_size >= OUT_ELEMS + ATTN_ELEMS) attn_out = out + OUT_ELEMS;

    static bool attr_set = false;
    if (!attr_set) {
        cudaFuncSetAttribute(attn_kernel,
                             cudaFuncAttributeMaxDynamicSharedMemorySize,
                             SM_TOT * 4);
        attr_set = true;
    }

    add_pe_kernel<<<MTOK * Edim / 256, 256>>>(x, xpe);

    // Fused Q/K/V projections: grid.y 0-3 -> Wq, 4-7 -> Wk, 8-11 -> Wv
    gemm_tc_kernel<<<dim3(MTOK / GBM, 12), 128>>>(
        xpe, Wq, bq, q, Wk, bk, k, Wv, bv, v);

    attn_kernel<<<dim3(Sdim / 32, Hn, Bz), 256, SM_TOT * 4>>>(
        q, k, v, ctx, attn_out);

    // Output projection: grid.y 0-3 -> Wo only
    gemm_tc_kernel<<<dim3(MTOK / GBM, 4), 128>>>(
        ctx, Wo, bo, out, Wo, bo, out, Wo, bo, out);
}

// round 11
// speedup vs baseline: 1.2780x; 1.2268x over previous
#include <cuda_runtime.h>
#include <cuda_bf16.h>
#include <math.h>
#include <stdint.h>

#define FULL 0xffffffffu

// Problem constants
#define Bz 2
#define Sdim 2048
#define Edim 256
#define Hn 8
#define HD 32
#define WIN 129
#define OFF 64
#define MTOK (Bz*Sdim)          // 4096 token rows
#define KW 128                  // packed k-words per 256 floats
#define WPK (128*256)           // u32 words per packed weight matrix

// Scratch (no cudaMalloc allowed)
__device__ uint32_t g_xh[MTOK*KW];   // x+pe, bf16 hi, k-packed pairs
__device__ uint32_t g_xl[MTOK*KW];   // bf16 lo
__device__ float    g_q[MTOK*Edim];
__device__ float    g_k[MTOK*Edim];
__device__ float    g_v[MTOK*Edim];
__device__ uint32_t g_ch[MTOK*KW];   // ctx bf16 hi packed
__device__ uint32_t g_cl[MTOK*KW];   // ctx bf16 lo packed
__device__ uint32_t g_wh[4*WPK];     // Wq,Wk,Wv,Wo packed [kp][n] bf16 hi
__device__ uint32_t g_wl[4*WPK];     // lo

// ---------------------------------------------------------------------------
// helpers
// ---------------------------------------------------------------------------
__device__ __forceinline__ void split_bf16(float x, uint16_t& h, uint16_t& l) {
    __nv_bfloat16 bh = __float2bfloat16_rn(x);
    float r = x - __bfloat162float(bh);
    __nv_bfloat16 bl = __float2bfloat16_rn(r);
    h = __bfloat16_as_ushort(bh);
    l = __bfloat16_as_ushort(bl);
}
__device__ __forceinline__ uint32_t pack2(uint16_t e0, uint16_t e1) {
    return (uint32_t)e0 | ((uint32_t)e1 << 16);
}
__device__ __forceinline__ void split_tf32(float x, uint32_t& hi, uint32_t& lo) {
    asm("cvt.rna.tf32.f32 %0, %1;" : "=r"(hi) : "f"(x));
    float l = x - __uint_as_float(hi);
    asm("cvt.rna.tf32.f32 %0, %1;" : "=r"(lo) : "f"(l));
}
__device__ __forceinline__ void mma_tf32(float* acc, const uint32_t* a, const uint32_t* b) {
    asm volatile(
        "mma.sync.aligned.m16n8k8.row.col.f32.tf32.tf32.f32 "
        "{%0,%1,%2,%3}, {%4,%5,%6,%7}, {%8,%9}, {%0,%1,%2,%3};\n"
        : "+f"(acc[0]), "+f"(acc[1]), "+f"(acc[2]), "+f"(acc[3])
        : "r"(a[0]), "r"(a[1]), "r"(a[2]), "r"(a[3]), "r"(b[0]), "r"(b[1]));
}
__device__ __forceinline__ void mma_bf16(float* acc, const uint32_t* a, const uint32_t* b) {
    asm volatile(
        "mma.sync.aligned.m16n8k16.row.col.f32.bf16.bf16.f32 "
        "{%0,%1,%2,%3}, {%4,%5,%6,%7}, {%8,%9}, {%0,%1,%2,%3};\n"
        : "+f"(acc[0]), "+f"(acc[1]), "+f"(acc[2]), "+f"(acc[3])
        : "r"(a[0]), "r"(a[1]), "r"(a[2]), "r"(a[3]), "r"(b[0]), "r"(b[1]));
}
__device__ __forceinline__ void cp16(void* smem, const void* g) {
    uint32_t s = (uint32_t)__cvta_generic_to_shared(smem);
    asm volatile("cp.async.cg.shared.global [%0], [%1], 16;\n" :: "r"(s), "l"(g));
}

// ---------------------------------------------------------------------------
// x + PE -> packed bf16 hi/lo pairs (one thread per k-pair)
// ---------------------------------------------------------------------------
__global__ void add_pe_pack_kernel(const float* __restrict__ x,
                                   uint32_t* __restrict__ yh,
                                   uint32_t* __restrict__ yl) {
    int i = blockIdx.x * 256 + threadIdx.x;   // MTOK*KW threads
    int e2 = i & (KW - 1);                    // pair index = e>>1
    int m  = i >> 7;
    int s  = m & (Sdim - 1);
    float dv = expf((float)e2 * (-2.0f * 9.210340371976184f / 256.0f));
    float ang = (float)s * dv;
    float2 xv = *(const float2*)&x[m * Edim + 2 * e2];
    float y0 = xv.x + sinf(ang);
    float y1 = xv.y + cosf(ang);
    uint16_t h0, l0, h1, l1;
    split_bf16(y0, h0, l0);
    split_bf16(y1, h1, l1);
    yh[i] = pack2(h0, h1);
    yl[i] = pack2(l0, l1);
}

// ---------------------------------------------------------------------------
// Pack the 4 weight matrices: word [kp][n] = (W[2kp][n], W[2kp+1][n]) bf16
// ---------------------------------------------------------------------------
__global__ void pack_w_kernel(const float* __restrict__ Wq, const float* __restrict__ Wk,
                              const float* __restrict__ Wv, const float* __restrict__ Wo,
                              uint32_t* __restrict__ wh, uint32_t* __restrict__ wl) {
    int i = blockIdx.x * 256 + threadIdx.x;     // 4*WPK threads
    int wsel = i >> 15;
    int r    = i & (WPK - 1);
    int kp   = r >> 8;
    int n    = r & 255;
    const float* W = (wsel == 0) ? Wq : ((wsel == 1) ? Wk : ((wsel == 2) ? Wv : Wo));
    float w0 = W[(2 * kp)     * Edim + n];
    float w1 = W[(2 * kp + 1) * Edim + n];
    uint16_t h0, l0, h1, l1;
    split_bf16(w0, h0, l0);
    split_bf16(w1, h1, l1);
    wh[i] = pack2(h0, h1);
    wl[i] = pack2(l0, l1);
}

// ---------------------------------------------------------------------------
// 3xBF16 tensor-core GEMM: Y[M,256] = X[M,256] @ W[256,256] + bias
// Operands pre-split/packed (bf16x2 words along k).
// CTA tile 64x64, 128 threads (4 warps, warp tile 32x32, 2x4 m16n8k16 frags).
// K chunk 16 (one MMA k-step per iter), 4-stage cp.async pipeline.
// ---------------------------------------------------------------------------
#define GBM 64
#define GBN 64
#define NSTAGE 4
#define PA 12    // A row stride in u32 (8 data + 4 pad, 16B-aligned, conflict-free)
#define PB 72    // B row stride in u32 (64 data + 8 pad, 16B-aligned, conflict-free)

__global__ __launch_bounds__(128) void gemm_tc_kernel(
    const uint32_t* __restrict__ Xh, const uint32_t* __restrict__ Xl,
    const uint32_t* __restrict__ Whb, const uint32_t* __restrict__ Wlb,
    const float* __restrict__ b0, float* __restrict__ Y0,
    const float* __restrict__ b1, float* __restrict__ Y1,
    const float* __restrict__ b2, float* __restrict__ Y2)
{
    __shared__ uint32_t Ahs[NSTAGE][GBM][PA];
    __shared__ uint32_t Als[NSTAGE][GBM][PA];
    __shared__ uint32_t Bhs[NSTAGE][8][PB];
    __shared__ uint32_t Bls[NSTAGE][8][PB];

    const int t    = threadIdx.x;
    const int lane = t & 31;
    const int warp = t >> 5;
    const int warp_m = warp & 1;
    const int warp_n = warp >> 1;
    const int lr = lane >> 2;
    const int lc = lane & 3;

    const int bm = blockIdx.x * GBM;
    const int wsel = blockIdx.y >> 2;
    const int bn = (blockIdx.y & 3) * GBN;

    const uint32_t* Wh = Whb + wsel * WPK;
    const uint32_t* Wl = Wlb + wsel * WPK;
    const float* bias  = (wsel == 0) ? b0 : ((wsel == 1) ? b1 : b2);
    float*       Y     = (wsel == 0) ? Y0 : ((wsel == 1) ? Y1 : Y2);

    float acc[2][4][4];
#pragma unroll
    for (int mf = 0; mf < 2; ++mf)
#pragma unroll
        for (int nf = 0; nf < 4; ++nf)
#pragma unroll
            for (int r = 0; r < 4; ++r) acc[mf][nf][r] = 0.f;

    // Loaders (128 thr): A 64x8 u32 (1 cp16/thr per half), B 8x64 u32 (same)
    const int am  = t >> 1;              // A row
    const int aq  = (t & 1) * 4;         // A word quad
    const int br  = t >> 4;              // B kp row
    const int bq  = (t & 15) * 4;        // B n quad

#define LOAD_TILE(it, buf)                                                     \
    do {                                                                       \
        int kw0 = (it) * 8;                                                    \
        cp16(&Ahs[buf][am][aq], &Xh[(bm + am) * KW + kw0 + aq]);               \
        cp16(&Als[buf][am][aq], &Xl[(bm + am) * KW + kw0 + aq]);               \
        cp16(&Bhs[buf][br][bq], &Wh[(kw0 + br) * Edim + bn + bq]);             \
        cp16(&Bls[buf][br][bq], &Wl[(kw0 + br) * Edim + bn + bq]);             \
        asm volatile("cp.async.commit_group;\n");                              \
    } while (0)

    const int KITERS = 16;
    LOAD_TILE(0, 0);
    LOAD_TILE(1, 1);
    LOAD_TILE(2, 2);

    for (int it = 0; it < KITERS; ++it) {
        const int buf = it & (NSTAGE - 1);
        const int rem = KITERS - 1 - it;
        if (rem >= 2)      asm volatile("cp.async.wait_group 2;\n");
        else if (rem == 1) asm volatile("cp.async.wait_group 1;\n");
        else               asm volatile("cp.async.wait_group 0;\n");
        __syncthreads();

        if (it + 3 < KITERS) LOAD_TILE(it + 3, (it + 3) & (NSTAGE - 1));

        uint32_t ah[2][4], al[2][4], bh[4][2], bl[4][2];
#pragma unroll
        for (int mf = 0; mf < 2; ++mf) {
            int r = warp_m * 32 + mf * 16 + lr;
            ah[mf][0] = Ahs[buf][r][lc];
            ah[mf][1] = Ahs[buf][r + 8][lc];
            ah[mf][2] = Ahs[buf][r][lc + 4];
            ah[mf][3] = Ahs[buf][r + 8][lc + 4];
            al[mf][0] = Als[buf][r][lc];
            al[mf][1] = Als[buf][r + 8][lc];
            al[mf][2] = Als[buf][r][lc + 4];
            al[mf][3] = Als[buf][r + 8][lc + 4];
        }
#pragma unroll
        for (int nf = 0; nf < 4; ++nf) {
            int cn = warp_n * 32 + nf * 8 + lr;
            bh[nf][0] = Bhs[buf][lc][cn];
            bh[nf][1] = Bhs[buf][lc + 4][cn];
            bl[nf][0] = Bls[buf][lc][cn];
            bl[nf][1] = Bls[buf][lc + 4][cn];
        }
#pragma unroll
        for (int mf = 0; mf < 2; ++mf)
#pragma unroll
            for (int nf = 0; nf < 4; ++nf) {
                mma_bf16(acc[mf][nf], al[mf], bh[nf]);   // lo*hi
                mma_bf16(acc[mf][nf], ah[mf], bl[nf]);   // hi*lo
                mma_bf16(acc[mf][nf], ah[mf], bh[nf]);   // hi*hi
            }
        __syncthreads();
    }

    // ---- epilogue: bias + store (same C layout as k8 mma) ----
#pragma unroll
    for (int mf = 0; mf < 2; ++mf) {
        int r = bm + warp_m * 32 + mf * 16 + lr;
#pragma unroll
        for (int nf = 0; nf < 4; ++nf) {
            int cg = bn + warp_n * 32 + nf * 8 + 2 * lc;
            float bv0 = bias[cg], bv1 = bias[cg + 1];
            float2 v0 = make_float2(acc[mf][nf][0] + bv0, acc[mf][nf][1] + bv1);
            float2 v1 = make_float2(acc[mf][nf][2] + bv0, acc[mf][nf][3] + bv1);
            *(float2*)&Y[r * Edim + cg] = v0;
            *(float2*)&Y[(r + 8) * Edim + cg] = v1;
        }
    }
#undef LOAD_TILE
}

// ---------------------------------------------------------------------------
// Tensor-core windowed attention (R8 math, tf32-3x). Emits ctx as PACKED
// bf16 hi/lo for the O projection.
// ---------------------------------------------------------------------------
#define KP 36     // k_sm / q_sm row pad
#define VP 40     // v_sm row pad
#define PP 164    // p_sm row pad
#define NROWS 160

#define SM_K 0
#define SM_V (SM_K + NROWS*KP)            // 5760
#define SM_Q (SM_V + NROWS*VP)            // 12160
#define SM_P (SM_Q + 32*KP)               // 13312
#define SM_RMAX (SM_P + 32*PP)            // 18560
#define SM_RSUM (SM_RMAX + 128)           // 18688
#define SM_TOT (SM_RSUM + 128)            // 18816 floats = 75264 B

__global__ __launch_bounds__(256) void attn_kernel(
    const float* __restrict__ q, const float* __restrict__ k,
    const float* __restrict__ v,
    uint32_t* __restrict__ ctx_h, uint32_t* __restrict__ ctx_l,
    float* __restrict__ attn_out)
{
    extern __shared__ float sm[];
    float* k_sm = sm + SM_K;
    float* v_sm = sm + SM_V;
    float* q_sm = sm + SM_Q;
    float* p_sm = sm + SM_P;
    float* rmax = sm + SM_RMAX;
    float* rsum = sm + SM_RSUM;

    const int b    = blockIdx.z;
    const int h    = blockIdx.y;
    const int s0   = blockIdx.x * 32;
    const int t    = threadIdx.x;
    const int lane = t & 31;
    const int warp = t >> 5;
    const int warp_m = warp & 1;
    const int warp_n = warp >> 1;
    const int lr = lane >> 2;
    const int lc = lane & 3;

    const int base = (b * Sdim) * Edim + h * HD;

#pragma unroll
    for (int it = 0; it < NROWS / 8; ++it) {
        int r = warp + it * 8;
        int tok = min(max(s0 - OFF + r, 0), Sdim - 1);
        int g = base + tok * Edim + lane;
        k_sm[r * KP + lane] = k[g];
        v_sm[r * VP + lane] = v[g];
    }
    {
        int qq = warp * 4;
#pragma unroll
        for (int i = 0; i < 4; ++i)
            q_sm[(qq + i) * KP + lane] = q[base + (s0 + qq + i) * Edim + lane];
    }
    __syncthreads();

    float acc[5][4];
#pragma unroll
    for (int nt = 0; nt < 5; ++nt)
#pragma unroll
        for (int j = 0; j < 4; ++j) acc[nt][j] = 0.f;

#pragma unroll
    for (int kt = 0; kt < 4; ++kt) {
        int kb = kt * 8 + lc;
        uint32_t ah[4], al[4];
        split_tf32(q_sm[(warp_m*16 + lr    ) * KP + kb    ], ah[0], al[0]);
        split_tf32(q_sm[(warp_m*16 + lr + 8) * KP + kb    ], ah[1], al[1]);
        split_tf32(q_sm[(warp_m*16 + lr    ) * KP + kb + 4], ah[2], al[2]);
        split_tf32(q_sm[(warp_m*16 + lr + 8) * KP + kb + 4], ah[3], al[3]);
#pragma unroll
        for (int nt = 0; nt < 5; ++nt) {
            int key = warp_n * 40 + nt * 8 + lr;
            uint32_t bh[2], bl[2];
            split_tf32(k_sm[key * KP + kb    ], bh[0], bl[0]);
            split_tf32(k_sm[key * KP + kb + 4], bh[1], bl[1]);
            mma_tf32(acc[nt], al, bh);
            mma_tf32(acc[nt], ah, bl);
            mma_tf32(acc[nt], ah, bh);
        }
    }

    const float scale = 0.17677669529663689f;  // 1/sqrt(32)
    const int q0 = warp_m * 16 + lr;
    const int q1 = q0 + 8;
    float m0 = -INFINITY, m1 = -INFINITY;
#pragma unroll
    for (int nt = 0; nt < 5; ++nt) {
#pragma unroll
        for (int j = 0; j < 4; ++j) {
            int row = (j >= 2) ? q1 : q0;
            int key = warp_n * 40 + nt * 8 + 2 * lc + (j & 1);
            int w  = key - row;
            int kg = s0 - OFF + key;
            bool valid = (w >= 0) & (w <= 128) & (kg >= 0) & (kg < Sdim);
            float s = valid ? acc[nt][j] * scale : -1e9f;
            acc[nt][j] = s;
            if (j >= 2) m1 = fmaxf(m1, s); else m0 = fmaxf(m0, s);
        }
    }
    m0 = fmaxf(m0, __shfl_xor_sync(FULL, m0, 1));
    m0 = fmaxf(m0, __shfl_xor_sync(FULL, m0, 2));
    m1 = fmaxf(m1, __shfl_xor_sync(FULL, m1, 1));
    m1 = fmaxf(m1, __shfl_xor_sync(FULL, m1, 2));
    if (lc == 0) { rmax[q0 * 4 + warp_n] = m0; rmax[q1 * 4 + warp_n] = m1; }
    __syncthreads();

    float4 t0 = *(const float4*)&rmax[q0 * 4];
    float4 t1 = *(const float4*)&rmax[q1 * 4];
    float gm0 = fmaxf(fmaxf(t0.x, t0.y), fmaxf(t0.z, t0.w));
    float gm1 = fmaxf(fmaxf(t1.x, t1.y), fmaxf(t1.z, t1.w));

    float sum0 = 0.f, sum1 = 0.f;
#pragma unroll
    for (int nt = 0; nt < 5; ++nt) {
#pragma unroll
        for (int j = 0; j < 4; ++j) {
            float e = expf(acc[nt][j] - ((j >= 2) ? gm1 : gm0));
            acc[nt][j] = e;
            if (j >= 2) sum1 += e; else sum0 += e;
        }
    }
    sum0 += __shfl_xor_sync(FULL, sum0, 1);
    sum0 += __shfl_xor_sync(FULL, sum0, 2);
    sum1 += __shfl_xor_sync(FULL, sum1, 1);
    sum1 += __shfl_xor_sync(FULL, sum1, 2);
    if (lc == 0) { rsum[q0 * 4 + warp_n] = sum0; rsum[q1 * 4 + warp_n] = sum1; }
    __syncthreads();

    float4 u0 = *(const float4*)&rsum[q0 * 4];
    float4 u1 = *(const float4*)&rsum[q1 * 4];
    float inv0 = 1.f / (u0.x + u0.y + u0.z + u0.w);
    float inv1 = 1.f / (u1.x + u1.y + u1.z + u1.w);

#pragma unroll
    for (int nt = 0; nt < 5; ++nt) {
#pragma unroll
        for (int j = 0; j < 4; ++j) {
            int row = (j >= 2) ? q1 : q0;
            int key = warp_n * 40 + nt * 8 + 2 * lc + (j & 1);
            p_sm[row * PP + key] = acc[nt][j] * ((j >= 2) ? inv1 : inv0);
        }
    }
    __syncthreads();

    if (attn_out) {
        int qrow = warp * 4;
#pragma unroll
        for (int i = 0; i < 4; ++i) {
            int qq = qrow + i;
            int arow = ((b * Hn + h) * Sdim + s0 + qq) * WIN;
#pragma unroll
            for (int j = 0; j < 4; ++j)
                attn_out[arow + lane + 32 * j] = p_sm[qq * PP + qq + lane + 32 * j];
            if (lane == 0)
                attn_out[arow + 128] = p_sm[qq * PP + qq + 128];
        }
    }

    float c[4] = {0.f, 0.f, 0.f, 0.f};
#pragma unroll
    for (int kt = 0; kt < 20; ++kt) {
        int kb = kt * 8 + lc;
        uint32_t ah[4], al[4], bh[2], bl[2];
        split_tf32(p_sm[q0 * PP + kb    ], ah[0], al[0]);
        split_tf32(p_sm[q1 * PP + kb    ], ah[1], al[1]);
        split_tf32(p_sm[q0 * PP + kb + 4], ah[2], al[2]);
        split_tf32(p_sm[q1 * PP + kb + 4], ah[3], al[3]);
        split_tf32(v_sm[(kb    ) * VP + warp_n * 8 + lr], bh[0], bl[0]);
        split_tf32(v_sm[(kb + 4) * VP + warp_n * 8 + lr], bh[1], bl[1]);
        mma_tf32(c, al, bh);
        mma_tf32(c, ah, bl);
        mma_tf32(c, ah, bh);
    }

    // ---- pack ctx to bf16 hi/lo words (c0,c1 and c2,c3 are k-adjacent) ----
    {
        int pkbase = (b * Sdim) * KW + h * (HD / 2);  // u32 index base
        int wd = warp_n * 4 + lc;                     // word within head
        uint16_t h0, l0, h1, l1;
        split_bf16(c[0], h0, l0);
        split_bf16(c[1], h1, l1);
        ctx_h[pkbase + (s0 + q0) * KW + wd] = pack2(h0, h1);
        ctx_l[pkbase + (s0 + q0) * KW + wd] = pack2(l0, l1);
        split_bf16(c[2], h0, l0);
        split_bf16(c[3], h1, l1);
        ctx_h[pkbase + (s0 + q1) * KW + wd] = pack2(h0, h1);
        ctx_l[pkbase + (s0 + q1) * KW + wd] = pack2(l0, l1);
    }
}

// ---------------------------------------------------------------------------
extern "C" void kernel_launch(void* const* d_in, const int* in_sizes, int n_in,
                              void* d_out, int out_size) {
    const float* x  = (const float*)d_in[0];
    const float* Wq = (const float*)d_in[1];
    const float* bq = (const float*)d_in[2];
    const float* Wk = (const float*)d_in[3];
    const float* bk = (const float*)d_in[4];
    const float* Wv = (const float*)d_in[5];
    const float* bv = (const float*)d_in[6];
    const float* Wo = (const float*)d_in[7];
    const float* bo = (const float*)d_in[8];
    float* out = (float*)d_out;

    uint32_t *xh, *xl, *ch, *cl, *wh, *wl;
    float *q, *k, *v;
    cudaGetSymbolAddress((void**)&xh, g_xh);
    cudaGetSymbolAddress((void**)&xl, g_xl);
    cudaGetSymbolAddress((void**)&q,  g_q);
    cudaGetSymbolAddress((void**)&k,  g_k);
    cudaGetSymbolAddress((void**)&v,  g_v);
    cudaGetSymbolAddress((void**)&ch, g_ch);
    cudaGetSymbolAddress((void**)&cl, g_cl);
    cudaGetSymbolAddress((void**)&wh, g_wh);
    cudaGetSymbolAddress((void**)&wl, g_wl);

    const long OUT_ELEMS  = (long)Bz * Sdim * Edim;                 // 1,048,576
    const long ATTN_ELEMS = (long)Bz * Hn * Sdim * WIN;             // 4,227,072
    float* attn_out = nullptr;
    if ((long)out_size >= OUT_ELEMS + ATTN_ELEMS) attn_out = out + OUT_ELEMS;

    static bool attr_set = false;
    if (!attr_set) {
        cudaFuncSetAttribute(attn_kernel,
                             cudaFuncAttributeMaxDynamicSharedMemorySize,
                             SM_TOT * 4);
        attr_set = true;
    }

    add_pe_pack_kernel<<<MTOK * KW / 256, 256>>>(x, xh, xl);
    pack_w_kernel<<<4 * WPK / 256, 256>>>(Wq, Wk, Wv, Wo, wh, wl);

    // Fused Q/K/V projections: grid.y 0-3 -> Wq, 4-7 -> Wk, 8-11 -> Wv
    gemm_tc_kernel<<<dim3(MTOK / GBM, 12), 128>>>(
        xh, xl, wh, wl, bq, q, bk, k, bv, v);

    attn_kernel<<<dim3(Sdim / 32, Hn, Bz), 256, SM_TOT * 4>>>(
        q, k, v, ch, cl, attn_out);

    // Output projection: grid.y 0-3 -> Wo (index 3 in packed weights)
    gemm_tc_kernel<<<dim3(MTOK / GBM, 4), 128>>>(
        ch, cl, wh + 3 * WPK, wl + 3 * WPK, bo, out, bo, out, bo, out);
}